// round 2
// baseline (speedup 1.0000x reference)
#include <cuda_runtime.h>
#include <math.h>

#define Bn 16
#define Tn 2048
#define Cn 1024
#define Hn 64
#define NSPLIT 4

// ---- static scratch ----
__device__ float g_qT[(size_t)Bn * Hn * Tn];      // [b][d][t]
__device__ float g_kT[(size_t)Bn * Hn * Tn];      // [b][d][t]
__device__ float g_v [(size_t)Bn * Tn * Hn];      // [b][t][d]
__device__ float g_ST[(size_t)Bn * Tn * Tn];      // [b][s][t]  stores P' = exp(S - m_tile)
__device__ float g_mpart[Bn * 16 * Tn];           // [b][t_tile][s]
__device__ float g_zpart[Bn * 16 * Tn];
__device__ float g_c[Bn * Tn];                    // logsumexp per (b,s)
__device__ float g_scale[Bn * 16 * Tn];           // exp(m_part - c) per [b][t_tile][s]
__device__ float g_opart[(size_t)NSPLIT * Bn * Tn * Hn];  // 32MB partials

// Fast exp via FMA-pipe polynomial. Valid for x <= 0.
__device__ __forceinline__ float fast_exp(float x) {
    float y = fmaxf(x * 1.4426950408889634f, -126.0f);
    float z = y + 12582912.0f;
    int   i = __float_as_int(z) - 0x4B400000;
    float f = y - (z - 12582912.0f);
    float p = 1.3333558146428443e-3f;
    p = fmaf(p, f, 9.618129107628477e-3f);
    p = fmaf(p, f, 5.550410866482158e-2f);
    p = fmaf(p, f, 2.402265069591007e-1f);
    p = fmaf(p, f, 6.931471805599453e-1f);
    p = fmaf(p, f, 1.0f);
    return __int_as_float(__float_as_int(p) + (i << 23));
}

// ---------------- K1: QKV projection, one matrix per blockIdx.y ----------------
// BM=128, BN=64, BK=32.  q,k -> transposed [b][d][t]; v -> [b][t][d].
__global__ __launch_bounds__(256) void qkv_kernel(
    const float* __restrict__ x,
    const float* __restrict__ Wq, const float* __restrict__ bq,
    const float* __restrict__ Wk, const float* __restrict__ bk,
    const float* __restrict__ Wv, const float* __restrict__ bv)
{
    __shared__ float Xs[32][132];   // [k][m]
    __shared__ float Ws[32][68];    // [k][n]
    const int tid = threadIdx.x;
    const int ty = tid & 15;        // m-chunk (8 rows)
    const int tx = tid >> 4;        // n-chunk (4 cols)
    const int m0 = ty * 8, n0 = tx * 4;
    const int mblk = blockIdx.x * 128;
    const int mat = blockIdx.y;
    const float* W  = (mat == 0) ? Wq : (mat == 1) ? Wk : Wv;
    const float* bs = (mat == 0) ? bq : (mat == 1) ? bk : bv;

    float acc[8][4];
    #pragma unroll
    for (int i = 0; i < 8; i++)
        #pragma unroll
        for (int j = 0; j < 4; j++) acc[i][j] = 0.0f;

    for (int k0 = 0; k0 < Cn; k0 += 32) {
        #pragma unroll
        for (int i = 0; i < 4; i++) {
            int idx = tid + i * 256;       // float4 index
            int mm  = idx >> 3;
            int kk  = (idx & 7) * 4;
            float4 vx = *(const float4*)(x + (size_t)(mblk + mm) * Cn + k0 + kk);
            Xs[kk    ][mm] = vx.x;
            Xs[kk + 1][mm] = vx.y;
            Xs[kk + 2][mm] = vx.z;
            Xs[kk + 3][mm] = vx.w;
        }
        #pragma unroll
        for (int i = 0; i < 2; i++) {
            int idx = tid + i * 256;       // f4 over 32x64
            int kk  = idx >> 4;
            int nf  = (idx & 15) * 4;
            *(float4*)&Ws[kk][nf] = *(const float4*)(W + (size_t)(k0 + kk) * Hn + nf);
        }
        __syncthreads();
        #pragma unroll 8
        for (int kk = 0; kk < 32; kk++) {
            float a[8], bb[4];
            *(float4*)&a[0] = *(float4*)&Xs[kk][m0];
            *(float4*)&a[4] = *(float4*)&Xs[kk][m0 + 4];
            *(float4*)&bb[0] = *(float4*)&Ws[kk][n0];
            #pragma unroll
            for (int i = 0; i < 8; i++)
                #pragma unroll
                for (int j = 0; j < 4; j++)
                    acc[i][j] = fmaf(a[i], bb[j], acc[i][j]);
        }
        __syncthreads();
    }

    const int b = mblk >> 11;
    const int tbase = (mblk & 2047) + m0;
    if (mat < 2) {
        float* base = (mat == 0) ? g_qT : g_kT;
        #pragma unroll
        for (int j = 0; j < 4; j++) {
            float bias = bs[n0 + j];
            float* dst = base + ((size_t)b * Hn + n0 + j) * Tn + tbase;
            float4 v0 = make_float4(acc[0][j] + bias, acc[1][j] + bias,
                                    acc[2][j] + bias, acc[3][j] + bias);
            float4 v1 = make_float4(acc[4][j] + bias, acc[5][j] + bias,
                                    acc[6][j] + bias, acc[7][j] + bias);
            *(float4*)(dst)     = v0;
            *(float4*)(dst + 4) = v1;
        }
    } else {
        float4 bias4 = *(const float4*)(bs + n0);
        #pragma unroll
        for (int i = 0; i < 8; i++) {
            float4 v = make_float4(acc[i][0] + bias4.x, acc[i][1] + bias4.y,
                                   acc[i][2] + bias4.z, acc[i][3] + bias4.w);
            *(float4*)(g_v + ((size_t)b * Tn + tbase + i) * Hn + n0) = v;
        }
    }
}

// ---------------- K2: S = Q K^T; store P' = exp(S - m_col_tile) + stats ----------------
__global__ __launch_bounds__(256) void scores_kernel()
{
    const int bt = blockIdx.x, bs = blockIdx.y, b = blockIdx.z;
    if (bt < bs) return;
    __shared__ float Qs[32][132];
    __shared__ float Ks[32][132];
    const int tid = threadIdx.x;
    const int ty = tid & 15;
    const int tx = tid >> 4;
    const int t0 = ty * 8, s0 = tx * 8;

    float acc[8][8];
    #pragma unroll
    for (int i = 0; i < 8; i++)
        #pragma unroll
        for (int j = 0; j < 8; j++) acc[i][j] = 0.0f;

    const float* qb = g_qT + (size_t)b * Hn * Tn;
    const float* kb = g_kT + (size_t)b * Hn * Tn;

    for (int kh = 0; kh < Hn; kh += 32) {
        #pragma unroll
        for (int i = 0; i < 4; i++) {
            int idx = tid + i * 256;
            int d   = idx >> 5;
            int c4  = (idx & 31) * 4;
            *(float4*)&Qs[d][c4] = *(const float4*)(qb + (size_t)(kh + d) * Tn + bt * 128 + c4);
            *(float4*)&Ks[d][c4] = *(const float4*)(kb + (size_t)(kh + d) * Tn + bs * 128 + c4);
        }
        __syncthreads();
        #pragma unroll 8
        for (int kk = 0; kk < 32; kk++) {
            float a[8], bb[8];
            *(float4*)&a[0]  = *(float4*)&Qs[kk][t0];
            *(float4*)&a[4]  = *(float4*)&Qs[kk][t0 + 4];
            *(float4*)&bb[0] = *(float4*)&Ks[kk][s0];
            *(float4*)&bb[4] = *(float4*)&Ks[kk][s0 + 4];
            #pragma unroll
            for (int i = 0; i < 8; i++)
                #pragma unroll
                for (int j = 0; j < 8; j++)
                    acc[i][j] = fmaf(a[i], bb[j], acc[i][j]);
        }
        __syncthreads();
    }

    const int gt0 = bt * 128 + t0;
    const int gs0 = bs * 128 + s0;
    #pragma unroll
    for (int i = 0; i < 8; i++)
        #pragma unroll
        for (int j = 0; j < 8; j++)
            if (gs0 + j > gt0 + i) acc[i][j] = -1e30f;

    float* STb = g_ST + (size_t)b * Tn * Tn;
    #pragma unroll
    for (int j = 0; j < 8; j++) {
        // column max over 128 t values (8 local + butterfly over 16 lanes)
        float m = acc[0][j];
        #pragma unroll
        for (int i = 1; i < 8; i++) m = fmaxf(m, acc[i][j]);
        #pragma unroll
        for (int off = 1; off < 16; off <<= 1)
            m = fmaxf(m, __shfl_xor_sync(0xffffffffu, m, off));
        // P' = exp(acc - m); also accumulate z
        float pv[8];
        float zv = 0.0f;
        #pragma unroll
        for (int i = 0; i < 8; i++) { pv[i] = fast_exp(acc[i][j] - m); zv += pv[i]; }
        #pragma unroll
        for (int off = 1; off < 16; off <<= 1)
            zv += __shfl_xor_sync(0xffffffffu, zv, off);
        float* dst = STb + (size_t)(gs0 + j) * Tn + gt0;
        *(float4*)(dst)     = make_float4(pv[0], pv[1], pv[2], pv[3]);
        *(float4*)(dst + 4) = make_float4(pv[4], pv[5], pv[6], pv[7]);
        if (ty == 0) {
            g_mpart[((size_t)b * 16 + bt) * Tn + gs0 + j] = m;
            g_zpart[((size_t)b * 16 + bt) * Tn + gs0 + j] = zv;
        }
    }
}

// ---------------- K2b: c[b][s] = logsumexp; g_scale[b][bt][s] = exp(m_bt - c) ----------------
__global__ __launch_bounds__(256) void stats_kernel()
{
    int idx = blockIdx.x * 256 + threadIdx.x;   // b*2048 + s
    int b = idx >> 11, s = idx & 2047;
    int bt0 = s >> 7;
    float m = -1e30f;
    for (int bt = bt0; bt < 16; bt++)
        m = fmaxf(m, g_mpart[((size_t)b * 16 + bt) * Tn + s]);
    float zv = 0.0f;
    for (int bt = bt0; bt < 16; bt++)
        zv += g_zpart[((size_t)b * 16 + bt) * Tn + s] *
              expf(g_mpart[((size_t)b * 16 + bt) * Tn + s] - m);
    float c = m + logf(zv);
    g_c[idx] = c;
    for (int bt = bt0; bt < 16; bt++)
        g_scale[((size_t)b * 16 + bt) * Tn + s] =
            expf(g_mpart[((size_t)b * 16 + bt) * Tn + s] - c);
}

// ---------------- K4: partial out over an s-split ----------------
// Block = 128 t x 64 d; s in [sp*512, min((bt+1)*128, sp*512+512))
__global__ __launch_bounds__(256) void out_kernel()
{
    const int bt = 15 - blockIdx.x;
    const int b  = blockIdx.y;
    const int sp = blockIdx.z;
    const int sBeg = sp * 512;
    const int sEnd = min((bt + 1) * 128, sBeg + 512);
    if (sBeg >= sEnd) return;

    __shared__ float Ps[32][132];
    __shared__ float Vs[32][64];
    const int tid = threadIdx.x;
    const int ty = tid & 15;
    const int tx = tid >> 4;
    const int t0 = ty * 8, d0 = tx * 4;

    float acc[8][4];
    #pragma unroll
    for (int i = 0; i < 8; i++)
        #pragma unroll
        for (int j = 0; j < 4; j++) acc[i][j] = 0.0f;

    const float* STb = g_ST + (size_t)b * Tn * Tn + bt * 128;
    const float* vb  = g_v  + (size_t)b * Tn * Hn;
    const float* scb = g_scale + ((size_t)b * 16 + bt) * Tn;

    for (int sg = sBeg; sg < sEnd; sg += 32) {
        #pragma unroll
        for (int i = 0; i < 4; i++) {
            int idx = tid + i * 256;
            int r   = idx >> 5;
            int c4  = (idx & 31) * 4;
            float sc = scb[sg + r];
            float4 sv = *(const float4*)(STb + (size_t)(sg + r) * Tn + c4);
            *(float4*)&Ps[r][c4] = make_float4(sv.x * sc, sv.y * sc, sv.z * sc, sv.w * sc);
        }
        #pragma unroll
        for (int i = 0; i < 2; i++) {
            int idx = tid + i * 256;
            int r   = idx >> 4;
            int c4  = (idx & 15) * 4;
            *(float4*)&Vs[r][c4] = *(const float4*)(vb + (size_t)(sg + r) * Hn + c4);
        }
        __syncthreads();
        #pragma unroll 8
        for (int ss = 0; ss < 32; ss++) {
            float a[8], bb[4];
            *(float4*)&a[0]  = *(float4*)&Ps[ss][t0];
            *(float4*)&a[4]  = *(float4*)&Ps[ss][t0 + 4];
            *(float4*)&bb[0] = *(float4*)&Vs[ss][d0];
            #pragma unroll
            for (int i = 0; i < 8; i++)
                #pragma unroll
                for (int j = 0; j < 4; j++)
                    acc[i][j] = fmaf(a[i], bb[j], acc[i][j]);
        }
        __syncthreads();
    }

    const int gt0 = bt * 128 + t0;
    #pragma unroll
    for (int i = 0; i < 8; i++) {
        float4 v = make_float4(acc[i][0], acc[i][1], acc[i][2], acc[i][3]);
        *(float4*)(g_opart + (((size_t)sp * Bn + b) * Tn + gt0 + i) * Hn + d0) = v;
    }
}

// ---------------- K5: reduce partials -> out ----------------
__global__ __launch_bounds__(256) void reduce_kernel(float* __restrict__ out)
{
    int idx = blockIdx.x * 256 + threadIdx.x;   // f4 index over 16*2048*64/4
    int d4 = idx & 15;
    int t  = (idx >> 4) & 2047;
    int b  = idx >> 15;
    int nsp = (t >> 9) + 1;                      // (t/128)/4 + 1
    float4 s = make_float4(0.f, 0.f, 0.f, 0.f);
    for (int sp = 0; sp < nsp; sp++) {
        float4 v = *(const float4*)(g_opart + (((size_t)sp * Bn + b) * Tn + t) * Hn + d4 * 4);
        s.x += v.x; s.y += v.y; s.z += v.z; s.w += v.w;
    }
    *(float4*)(out + (((size_t)b * Tn + t) * Hn) + d4 * 4) = s;
}

extern "C" void kernel_launch(void* const* d_in, const int* in_sizes, int n_in,
                              void* d_out, int out_size)
{
    const float* x  = (const float*)d_in[0];
    const float* Wq = (const float*)d_in[1];
    const float* bq = (const float*)d_in[2];
    const float* Wk = (const float*)d_in[3];
    const float* bk = (const float*)d_in[4];
    const float* Wv = (const float*)d_in[5];
    const float* bv = (const float*)d_in[6];
    float* out = (float*)d_out;

    qkv_kernel<<<dim3(256, 3), 256>>>(x, Wq, bq, Wk, bk, Wv, bv);
    scores_kernel<<<dim3(16, 16, 16), 256>>>();
    stats_kernel<<<128, 256>>>();
    out_kernel<<<dim3(16, 16, NSPLIT), 256>>>();
    reduce_kernel<<<2048, 256>>>(out);
}

// round 4
// speedup vs baseline: 2.0649x; 2.0649x over previous
#include <cuda_runtime.h>
#include <cuda_bf16.h>
#include <cstdint>

#define Bn 16
#define Tn 2048
#define Cn 1024
#define Hn 64
#define LD 72          // smem row stride (elems) for 64-wide bf16 tiles

// ---------------- static scratch ----------------
__device__ __nv_bfloat16 g_qh[(size_t)Bn * Tn * Hn];
__device__ __nv_bfloat16 g_ql[(size_t)Bn * Tn * Hn];
__device__ __nv_bfloat16 g_kh[(size_t)Bn * Tn * Hn];
__device__ __nv_bfloat16 g_kl[(size_t)Bn * Tn * Hn];
__device__ __nv_bfloat16 g_vh[(size_t)Bn * Hn * Tn];   // transposed [b][d][t]
__device__ __nv_bfloat16 g_vl[(size_t)Bn * Hn * Tn];
__device__ __nv_bfloat16 g_Ph[(size_t)Bn * Tn * Tn];   // P' = exp(S), [b][t][s], hi
__device__ __nv_bfloat16 g_Pl[(size_t)Bn * Tn * Tn];   // lo
__device__ float g_z[(size_t)Bn * 16 * Tn];            // per-(b,bt-tile) column sumexp
__device__ float g_sc[Bn * Tn];                        // 1 / sum_bt z
__device__ float g_opart[(size_t)2 * Bn * Tn * Hn];    // split-s partials

// ---------------- helpers ----------------
__device__ __forceinline__ uint32_t smem_u32(const void* p) {
    uint32_t a;
    asm("{ .reg .u64 t; cvta.to.shared.u64 t, %1; cvt.u32.u64 %0, t; }" : "=r"(a) : "l"(p));
    return a;
}
__device__ __forceinline__ void ldsm_x4(uint32_t& r0, uint32_t& r1, uint32_t& r2, uint32_t& r3, uint32_t a) {
    asm volatile("ldmatrix.sync.aligned.m8n8.x4.shared.b16 {%0,%1,%2,%3}, [%4];"
                 : "=r"(r0), "=r"(r1), "=r"(r2), "=r"(r3) : "r"(a));
}
__device__ __forceinline__ void mma_bf16(float* c, uint32_t a0, uint32_t a1, uint32_t a2, uint32_t a3,
                                         uint32_t b0, uint32_t b1) {
    asm volatile("mma.sync.aligned.m16n8k16.row.col.f32.bf16.bf16.f32 "
                 "{%0,%1,%2,%3},{%4,%5,%6,%7},{%8,%9},{%0,%1,%2,%3};"
                 : "+f"(c[0]), "+f"(c[1]), "+f"(c[2]), "+f"(c[3])
                 : "r"(a0), "r"(a1), "r"(a2), "r"(a3), "r"(b0), "r"(b1));
}
__device__ __forceinline__ uint32_t pack_bf2(__nv_bfloat16 a, __nv_bfloat16 b) {
    unsigned short ua = *reinterpret_cast<unsigned short*>(&a);
    unsigned short ub = *reinterpret_cast<unsigned short*>(&b);
    return ((uint32_t)ub << 16) | ua;
}
// fast exp on FMA pipe; valid for x in (-inf, ~87]
__device__ __forceinline__ float fast_exp(float x) {
    float y = fmaxf(x * 1.4426950408889634f, -126.0f);
    float z = y + 12582912.0f;
    int   i = __float_as_int(z) - 0x4B400000;
    float f = y - (z - 12582912.0f);
    float p = 1.3333558146428443e-3f;
    p = fmaf(p, f, 9.618129107628477e-3f);
    p = fmaf(p, f, 5.550410866482158e-2f);
    p = fmaf(p, f, 2.402265069591007e-1f);
    p = fmaf(p, f, 6.931471805599453e-1f);
    p = fmaf(p, f, 1.0f);
    return __int_as_float(__float_as_int(p) + (i << 23));
}
__device__ __forceinline__ void split2(float v, __nv_bfloat16& h, __nv_bfloat16& l) {
    h = __float2bfloat16(v);
    l = __float2bfloat16(v - __bfloat162float(h));
}

// ================= K1: QKV projection =================
#define QK_SMEM ((128 * LD + 128 * LD + 64 * LD + 64 * LD) * 2)
__global__ __launch_bounds__(256) void qkv_kernel(
    const float* __restrict__ x,
    const float* __restrict__ Wq, const float* __restrict__ bq,
    const float* __restrict__ Wk, const float* __restrict__ bk,
    const float* __restrict__ Wv, const float* __restrict__ bv)
{
    extern __shared__ char sm[];
    __nv_bfloat16* Ah = (__nv_bfloat16*)sm;          // [128][LD]
    __nv_bfloat16* Al = Ah + 128 * LD;
    __nv_bfloat16* Bh = Al + 128 * LD;               // [64][LD]
    __nv_bfloat16* Bl = Bh + 64 * LD;
    const int tid = threadIdx.x, lane = tid & 31, wid = tid >> 5;
    const int wm = wid & 3, wn = wid >> 2;
    const int mb = blockIdx.x * 128;
    const int mat = blockIdx.y;
    const float* W  = (mat == 0) ? Wq : (mat == 1) ? Wk : Wv;
    const float* bp = (mat == 0) ? bq : (mat == 1) ? bk : bv;

    const uint32_t sAh = smem_u32(Ah), sAl = smem_u32(Al);
    const uint32_t sBh = smem_u32(Bh), sBl = smem_u32(Bl);
    const int lr = lane & 15, lc = (lane & 16) >> 1;             // A frag row/col offsets
    const int br = (lane & 7) + ((lane & 16) >> 1), bc = lane & 8; // B frag row/col offsets

    float acc[2][4][4];
    #pragma unroll
    for (int m = 0; m < 2; m++)
        #pragma unroll
        for (int j = 0; j < 4; j++)
            #pragma unroll
            for (int e = 0; e < 4; e++) acc[m][j][e] = 0.0f;

    for (int ch = 0; ch < 16; ch++) {
        const int k0c = ch * 64;
        #pragma unroll
        for (int i = 0; i < 8; i++) {
            int idx = tid + i * 256;
            int row = idx >> 4, c4 = (idx & 15) * 4;
            float4 v = *(const float4*)(x + (size_t)(mb + row) * Cn + k0c + c4);
            __nv_bfloat16 h, l;
            split2(v.x, h, l); Ah[row * LD + c4]     = h; Al[row * LD + c4]     = l;
            split2(v.y, h, l); Ah[row * LD + c4 + 1] = h; Al[row * LD + c4 + 1] = l;
            split2(v.z, h, l); Ah[row * LD + c4 + 2] = h; Al[row * LD + c4 + 2] = l;
            split2(v.w, h, l); Ah[row * LD + c4 + 3] = h; Al[row * LD + c4 + 3] = l;
        }
        #pragma unroll
        for (int i = 0; i < 4; i++) {
            int idx = tid + i * 256;
            int k = idx >> 4, n4 = (idx & 15) * 4;
            float4 w = *(const float4*)(W + (size_t)(k0c + k) * Hn + n4);
            __nv_bfloat16 h, l;
            split2(w.x, h, l); Bh[(n4)     * LD + k] = h; Bl[(n4)     * LD + k] = l;
            split2(w.y, h, l); Bh[(n4 + 1) * LD + k] = h; Bl[(n4 + 1) * LD + k] = l;
            split2(w.z, h, l); Bh[(n4 + 2) * LD + k] = h; Bl[(n4 + 2) * LD + k] = l;
            split2(w.w, h, l); Bh[(n4 + 3) * LD + k] = h; Bl[(n4 + 3) * LD + k] = l;
        }
        __syncthreads();
        #pragma unroll
        for (int ks = 0; ks < 4; ks++) {
            const int k0 = ks * 16;
            uint32_t ah[2][4], al[2][4], bh[2][4], bl[2][4];
            #pragma unroll
            for (int m = 0; m < 2; m++) {
                uint32_t ra = (uint32_t)(((wm * 32 + m * 16 + lr) * LD + k0 + lc) * 2);
                ldsm_x4(ah[m][0], ah[m][1], ah[m][2], ah[m][3], sAh + ra);
                ldsm_x4(al[m][0], al[m][1], al[m][2], al[m][3], sAl + ra);
            }
            #pragma unroll
            for (int g = 0; g < 2; g++) {
                uint32_t rb = (uint32_t)(((wn * 32 + g * 16 + br) * LD + k0 + bc) * 2);
                ldsm_x4(bh[g][0], bh[g][1], bh[g][2], bh[g][3], sBh + rb);
                ldsm_x4(bl[g][0], bl[g][1], bl[g][2], bl[g][3], sBl + rb);
            }
            #pragma unroll
            for (int m = 0; m < 2; m++)
                #pragma unroll
                for (int j = 0; j < 4; j++) {
                    uint32_t b0h = bh[j >> 1][(j & 1) * 2], b1h = bh[j >> 1][(j & 1) * 2 + 1];
                    uint32_t b0l = bl[j >> 1][(j & 1) * 2], b1l = bl[j >> 1][(j & 1) * 2 + 1];
                    mma_bf16(acc[m][j], ah[m][0], ah[m][1], ah[m][2], ah[m][3], b0h, b1h);
                    mma_bf16(acc[m][j], al[m][0], al[m][1], al[m][2], al[m][3], b0h, b1h);
                    mma_bf16(acc[m][j], ah[m][0], ah[m][1], ah[m][2], ah[m][3], b0l, b1l);
                }
        }
        __syncthreads();
    }

    const int quad = lane >> 2, pair = lane & 3;
    const int b = mb >> 11, tloc0 = mb & 2047;
    if (mat < 2) {
        uint32_t* dh = (uint32_t*)(mat == 0 ? g_qh : g_kh);
        uint32_t* dl = (uint32_t*)(mat == 0 ? g_ql : g_kl);
        #pragma unroll
        for (int m = 0; m < 2; m++)
            #pragma unroll
            for (int rr = 0; rr < 2; rr++)
                #pragma unroll
                for (int j = 0; j < 4; j++) {
                    int row = wm * 32 + m * 16 + rr * 8 + quad;
                    int col = wn * 32 + j * 8 + 2 * pair;
                    float v0 = acc[m][j][rr * 2]     + bp[col];
                    float v1 = acc[m][j][rr * 2 + 1] + bp[col + 1];
                    __nv_bfloat16 h0, l0, h1, l1;
                    split2(v0, h0, l0); split2(v1, h1, l1);
                    size_t o = (size_t)(mb + row) * 32 + (col >> 1);
                    dh[o] = pack_bf2(h0, h1);
                    dl[o] = pack_bf2(l0, l1);
                }
    } else {
        __nv_bfloat16* Th = Ah;   // [64][132]
        __nv_bfloat16* Tl = Al;
        #pragma unroll
        for (int m = 0; m < 2; m++)
            #pragma unroll
            for (int rr = 0; rr < 2; rr++)
                #pragma unroll
                for (int j = 0; j < 4; j++) {
                    int row = wm * 32 + m * 16 + rr * 8 + quad;
                    int col = wn * 32 + j * 8 + 2 * pair;
                    float v0 = acc[m][j][rr * 2]     + bp[col];
                    float v1 = acc[m][j][rr * 2 + 1] + bp[col + 1];
                    __nv_bfloat16 h, l;
                    split2(v0, h, l); Th[col * 132 + row] = h; Tl[col * 132 + row] = l;
                    split2(v1, h, l); Th[(col + 1) * 132 + row] = h; Tl[(col + 1) * 132 + row] = l;
                }
        __syncthreads();
        uint32_t* vh32 = (uint32_t*)g_vh;
        uint32_t* vl32 = (uint32_t*)g_vl;
        const uint32_t* th32 = (const uint32_t*)Th;
        const uint32_t* tl32 = (const uint32_t*)Tl;
        #pragma unroll
        for (int i = 0; i < 16; i++) {
            int idx = tid + i * 256;
            int d = idx >> 6, t2 = idx & 63;
            size_t o = (size_t)(b * 64 + d) * 1024 + (tloc0 >> 1) + t2;
            vh32[o] = th32[d * 66 + t2];
            vl32[o] = tl32[d * 66 + t2];
        }
    }
}

// ================= K2: scores -> P' = exp(S) + column z =================
#define SC_BF (4 * 128 * LD)              // elems of bf16
#define SC_SMEM (SC_BF * 2 + 4 * 128 * 4)
__global__ __launch_bounds__(256) void scores_kernel()
{
    const int bt = blockIdx.x, bs = blockIdx.y, b = blockIdx.z;
    if (bt < bs) return;
    extern __shared__ char sm[];
    __nv_bfloat16* Qh = (__nv_bfloat16*)sm;          // [128][LD]
    __nv_bfloat16* Ql = Qh + 128 * LD;
    __nv_bfloat16* Kh = Ql + 128 * LD;
    __nv_bfloat16* Kl = Kh + 128 * LD;
    float* zbuf = (float*)(Kl + 128 * LD);           // [4][128]

    const int tid = threadIdx.x, lane = tid & 31, wid = tid >> 5;
    const int wm = wid & 3, wn = wid >> 2;
    const int lr = lane & 15, lc = (lane & 16) >> 1;
    const int br = (lane & 7) + ((lane & 16) >> 1), bc = lane & 8;
    const int quad = lane >> 2, pair = lane & 3;

    {
        const uint4* qh = (const uint4*)(g_qh + ((size_t)b * Tn + bt * 128) * Hn);
        const uint4* ql = (const uint4*)(g_ql + ((size_t)b * Tn + bt * 128) * Hn);
        const uint4* kh = (const uint4*)(g_kh + ((size_t)b * Tn + bs * 128) * Hn);
        const uint4* kl = (const uint4*)(g_kl + ((size_t)b * Tn + bs * 128) * Hn);
        #pragma unroll
        for (int i = 0; i < 4; i++) {
            int idx = tid + i * 256;
            int row = idx >> 3, u = idx & 7;
            *(uint4*)&Qh[row * LD + u * 8] = qh[idx];
            *(uint4*)&Ql[row * LD + u * 8] = ql[idx];
            *(uint4*)&Kh[row * LD + u * 8] = kh[idx];
            *(uint4*)&Kl[row * LD + u * 8] = kl[idx];
        }
    }
    __syncthreads();

    const uint32_t sQh = smem_u32(Qh), sQl = smem_u32(Ql);
    const uint32_t sKh = smem_u32(Kh), sKl = smem_u32(Kl);

    float acc[2][8][4];
    #pragma unroll
    for (int m = 0; m < 2; m++)
        #pragma unroll
        for (int j = 0; j < 8; j++)
            #pragma unroll
            for (int e = 0; e < 4; e++) acc[m][j][e] = 0.0f;

    #pragma unroll
    for (int ks = 0; ks < 4; ks++) {
        const int k0 = ks * 16;
        uint32_t ah[2][4], al[2][4], bh[4][4], bl[4][4];
        #pragma unroll
        for (int m = 0; m < 2; m++) {
            uint32_t ra = (uint32_t)(((wm * 32 + m * 16 + lr) * LD + k0 + lc) * 2);
            ldsm_x4(ah[m][0], ah[m][1], ah[m][2], ah[m][3], sQh + ra);
            ldsm_x4(al[m][0], al[m][1], al[m][2], al[m][3], sQl + ra);
        }
        #pragma unroll
        for (int g = 0; g < 4; g++) {
            uint32_t rb = (uint32_t)(((wn * 64 + g * 16 + br) * LD + k0 + bc) * 2);
            ldsm_x4(bh[g][0], bh[g][1], bh[g][2], bh[g][3], sKh + rb);
            ldsm_x4(bl[g][0], bl[g][1], bl[g][2], bl[g][3], sKl + rb);
        }
        #pragma unroll
        for (int m = 0; m < 2; m++)
            #pragma unroll
            for (int j = 0; j < 8; j++) {
                uint32_t b0h = bh[j >> 1][(j & 1) * 2], b1h = bh[j >> 1][(j & 1) * 2 + 1];
                uint32_t b0l = bl[j >> 1][(j & 1) * 2], b1l = bl[j >> 1][(j & 1) * 2 + 1];
                mma_bf16(acc[m][j], ah[m][0], ah[m][1], ah[m][2], ah[m][3], b0h, b1h);
                mma_bf16(acc[m][j], al[m][0], al[m][1], al[m][2], al[m][3], b0h, b1h);
                mma_bf16(acc[m][j], ah[m][0], ah[m][1], ah[m][2], ah[m][3], b0l, b1l);
            }
    }

    // epilogue: mask, exp, store P', column z
    uint32_t* Ph32 = (uint32_t*)g_Ph;
    uint32_t* Pl32 = (uint32_t*)g_Pl;
    float zc[2] = {0.0f, 0.0f};   // per-thread partial for its two column families... per j below
    #pragma unroll
    for (int j = 0; j < 8; j++) {
        float z0 = 0.0f, z1 = 0.0f;
        #pragma unroll
        for (int m = 0; m < 2; m++)
            #pragma unroll
            for (int rr = 0; rr < 2; rr++) {
                int trow = bt * 128 + wm * 32 + m * 16 + rr * 8 + quad;
                int scol = bs * 128 + wn * 64 + j * 8 + 2 * pair;
                float s0 = acc[m][j][rr * 2], s1 = acc[m][j][rr * 2 + 1];
                float p0 = (scol     <= trow) ? fast_exp(s0) : 0.0f;
                float p1 = (scol + 1 <= trow) ? fast_exp(s1) : 0.0f;
                z0 += p0; z1 += p1;
                __nv_bfloat16 h0, l0, h1, l1;
                split2(p0, h0, l0); split2(p1, h1, l1);
                size_t o = ((size_t)b * Tn + trow) * 1024 + (scol >> 1);
                Ph32[o] = pack_bf2(h0, h1);
                Pl32[o] = pack_bf2(l0, l1);
            }
        #pragma unroll
        for (int off = 4; off < 32; off <<= 1) {
            z0 += __shfl_xor_sync(0xffffffffu, z0, off);
            z1 += __shfl_xor_sync(0xffffffffu, z1, off);
        }
        if (quad == 0) {
            int colloc = wn * 64 + j * 8 + 2 * pair;
            zbuf[wm * 128 + colloc]     = z0;
            zbuf[wm * 128 + colloc + 1] = z1;
        }
    }
    (void)zc;
    __syncthreads();
    if (tid < 128) {
        float z = zbuf[tid] + zbuf[128 + tid] + zbuf[256 + tid] + zbuf[384 + tid];
        g_z[((size_t)b * 16 + bt) * Tn + bs * 128 + tid] = z;
    }
}

// ================= K3: sc[b][s] = 1 / sum_bt z =================
__global__ __launch_bounds__(256) void cmerge_kernel()
{
    int idx = blockIdx.x * 256 + threadIdx.x;   // b*2048 + s
    int b = idx >> 11, s = idx & 2047;
    float z = 0.0f;
    for (int bt = s >> 7; bt < 16; bt++)
        z += g_z[((size_t)b * 16 + bt) * Tn + s];
    g_sc[idx] = 1.0f / z;
}

// ================= K4: out = (P'*sc) @ V^T, split-s partials =================
#define OUT_SMEM ((128 * LD + 128 * LD + 64 * LD + 64 * LD) * 2)
__global__ __launch_bounds__(256) void out_kernel()
{
    const int bt = 15 - blockIdx.x;
    const int b  = blockIdx.y;
    const int sp = blockIdx.z;
    const int sBeg = sp * 1024;
    const int sEnd = min((bt + 1) * 128, sBeg + 1024);
    if (sBeg >= sEnd) return;

    extern __shared__ char sm[];
    __nv_bfloat16* Ph = (__nv_bfloat16*)sm;          // [128][LD]
    __nv_bfloat16* Pl = Ph + 128 * LD;
    __nv_bfloat16* Vh = Pl + 128 * LD;               // [64][LD]
    __nv_bfloat16* Vl = Vh + 64 * LD;

    const int tid = threadIdx.x, lane = tid & 31, wid = tid >> 5;
    const int wm = wid & 3, wn = wid >> 2;
    const int lr = lane & 15, lc = (lane & 16) >> 1;
    const int br = (lane & 7) + ((lane & 16) >> 1), bc = lane & 8;
    const int quad = lane >> 2, pair = lane & 3;

    const uint32_t sPh = smem_u32(Ph), sPl = smem_u32(Pl);
    const uint32_t sVh = smem_u32(Vh), sVl = smem_u32(Vl);
    const uint32_t* gPh = (const uint32_t*)g_Ph;
    const uint32_t* gPl = (const uint32_t*)g_Pl;
    const uint32_t* gVh = (const uint32_t*)g_vh;
    const uint32_t* gVl = (const uint32_t*)g_vl;

    float acc[2][4][4];
    #pragma unroll
    for (int m = 0; m < 2; m++)
        #pragma unroll
        for (int j = 0; j < 4; j++)
            #pragma unroll
            for (int e = 0; e < 4; e++) acc[m][j][e] = 0.0f;

    for (int sg = sBeg; sg < sEnd; sg += 64) {
        // stage P (scaled, re-split)
        #pragma unroll
        for (int i = 0; i < 16; i++) {
            int idx = tid + i * 256;
            int row = idx >> 5, c2 = idx & 31;
            int s0 = sg + c2 * 2;
            size_t o = ((size_t)b * Tn + bt * 128 + row) * 1024 + (s0 >> 1);
            uint32_t hw = gPh[o], lw = gPl[o];
            __nv_bfloat162 hb = *(__nv_bfloat162*)&hw;
            __nv_bfloat162 lb = *(__nv_bfloat162*)&lw;
            float sc0 = g_sc[b * Tn + s0], sc1 = g_sc[b * Tn + s0 + 1];
            float p0 = (__low2float(hb)  + __low2float(lb))  * sc0;
            float p1 = (__high2float(hb) + __high2float(lb)) * sc1;
            __nv_bfloat16 h0, l0, h1, l1;
            split2(p0, h0, l0); split2(p1, h1, l1);
            *(uint32_t*)&Ph[row * LD + c2 * 2] = pack_bf2(h0, h1);
            *(uint32_t*)&Pl[row * LD + c2 * 2] = pack_bf2(l0, l1);
        }
        // stage V^T chunk: rows d=64, cols s
        #pragma unroll
        for (int i = 0; i < 8; i++) {
            int idx = tid + i * 256;
            int d = idx >> 5, c2 = idx & 31;
            size_t o = (size_t)(b * 64 + d) * 1024 + (sg >> 1) + c2;
            *(uint32_t*)&Vh[d * LD + c2 * 2] = gVh[o];
            *(uint32_t*)&Vl[d * LD + c2 * 2] = gVl[o];
        }
        __syncthreads();
        #pragma unroll
        for (int ks = 0; ks < 4; ks++) {
            const int k0 = ks * 16;
            uint32_t ah[2][4], al[2][4], bh[2][4], bl[2][4];
            #pragma unroll
            for (int m = 0; m < 2; m++) {
                uint32_t ra = (uint32_t)(((wm * 32 + m * 16 + lr) * LD + k0 + lc) * 2);
                ldsm_x4(ah[m][0], ah[m][1], ah[m][2], ah[m][3], sPh + ra);
                ldsm_x4(al[m][0], al[m][1], al[m][2], al[m][3], sPl + ra);
            }
            #pragma unroll
            for (int g = 0; g < 2; g++) {
                uint32_t rb = (uint32_t)(((wn * 32 + g * 16 + br) * LD + k0 + bc) * 2);
                ldsm_x4(bh[g][0], bh[g][1], bh[g][2], bh[g][3], sVh + rb);
                ldsm_x4(bl[g][0], bl[g][1], bl[g][2], bl[g][3], sVl + rb);
            }
            #pragma unroll
            for (int m = 0; m < 2; m++)
                #pragma unroll
                for (int j = 0; j < 4; j++) {
                    uint32_t b0h = bh[j >> 1][(j & 1) * 2], b1h = bh[j >> 1][(j & 1) * 2 + 1];
                    uint32_t b0l = bl[j >> 1][(j & 1) * 2], b1l = bl[j >> 1][(j & 1) * 2 + 1];
                    mma_bf16(acc[m][j], ah[m][0], ah[m][1], ah[m][2], ah[m][3], b0h, b1h);
                    mma_bf16(acc[m][j], al[m][0], al[m][1], al[m][2], al[m][3], b0h, b1h);
                    mma_bf16(acc[m][j], ah[m][0], ah[m][1], ah[m][2], ah[m][3], b0l, b1l);
                }
        }
        __syncthreads();
    }

    #pragma unroll
    for (int m = 0; m < 2; m++)
        #pragma unroll
        for (int rr = 0; rr < 2; rr++)
            #pragma unroll
            for (int j = 0; j < 4; j++) {
                int row = bt * 128 + wm * 32 + m * 16 + rr * 8 + quad;
                int col = wn * 32 + j * 8 + 2 * pair;
                float2 v = make_float2(acc[m][j][rr * 2], acc[m][j][rr * 2 + 1]);
                *(float2*)(g_opart + (((size_t)sp * Bn + b) * Tn + row) * Hn + col) = v;
            }
}

// ================= K5: reduce partials =================
__global__ __launch_bounds__(256) void reduce_kernel(float* __restrict__ out)
{
    int idx = blockIdx.x * 256 + threadIdx.x;   // f4 index
    int d4 = idx & 15;
    int t  = (idx >> 4) & 2047;
    int b  = idx >> 15;
    float4 s = *(const float4*)(g_opart + (((size_t)0 * Bn + b) * Tn + t) * Hn + d4 * 4);
    if (t >= 1024) {
        float4 v = *(const float4*)(g_opart + (((size_t)1 * Bn + b) * Tn + t) * Hn + d4 * 4);
        s.x += v.x; s.y += v.y; s.z += v.z; s.w += v.w;
    }
    *(float4*)(out + ((size_t)b * Tn + t) * Hn + d4 * 4) = s;
}

extern "C" void kernel_launch(void* const* d_in, const int* in_sizes, int n_in,
                              void* d_out, int out_size)
{
    const float* x  = (const float*)d_in[0];
    const float* Wq = (const float*)d_in[1];
    const float* bq = (const float*)d_in[2];
    const float* Wk = (const float*)d_in[3];
    const float* bk = (const float*)d_in[4];
    const float* Wv = (const float*)d_in[5];
    const float* bv = (const float*)d_in[6];
    float* out = (float*)d_out;

    cudaFuncSetAttribute(qkv_kernel,    cudaFuncAttributeMaxDynamicSharedMemorySize, QK_SMEM);
    cudaFuncSetAttribute(scores_kernel, cudaFuncAttributeMaxDynamicSharedMemorySize, SC_SMEM);
    cudaFuncSetAttribute(out_kernel,    cudaFuncAttributeMaxDynamicSharedMemorySize, OUT_SMEM);

    qkv_kernel<<<dim3(256, 3), 256, QK_SMEM>>>(x, Wq, bq, Wk, bk, Wv, bv);
    scores_kernel<<<dim3(16, 16, 16), 256, SC_SMEM>>>();
    cmerge_kernel<<<128, 256>>>();
    out_kernel<<<dim3(16, 16, 2), 256, OUT_SMEM>>>();
    reduce_kernel<<<2048, 256>>>(out);
}